// round 15
// baseline (speedup 1.0000x reference)
#include <cuda_runtime.h>
#include <cstdint>

// DiffKS fused, warp-autonomous, 16 warps/SM: FIR (order 6) + order-2 IIR via
// warp affine scan (8 samples/thread). NO block barriers (R14 lesson: convoying
// was the limit). This version: smem stages hold Ae ONLY (quad pitch 25,
// 6.4KB/stage, double-buffered, 12.8KB/warp -> 4 CTAs/SM); y lives in
// registers (own 2 f4-groups/thread, FIR halo via shfl_up from lane-1, lane 0
// from previous tile's lane-31 regs; exact), Al register double-buffered.
// IIR state chains in registers via lane-31 composite map (exact). Row starts
// reset state to exact zero; a mid-row span start runs one 32-sample warmup
// (|a|<=0.25 -> contraction ~0.64/step -> ~6e-7 << 1e-3).

#define BATCH 48
#define TLEN  88200
#define T4    22050
#define Y_F4_ROW  22050
#define AE_F4_ROW 132300
#define AL_F4_ROW 44100
#define YMAX  (Y_F4_ROW - 1)

#define TPB    128
#define TROW   345                   // 64-f4 warp-tiles per row
#define NTILES (BATCH * TROW)        // 16560
#define GRID   592                   // 148 SMs * 4 CTAs
#define NWARPS (GRID * 4)            // 2368 autonomous warps (~7 tiles each)
#define FULLM  0xffffffffu

// per-warp stage: Ae only, 16 quads * pitch 25 = 400 f4 (6.4 KB)
#define STAGE_F4   400
#define WARP_F4    (2 * STAGE_F4)    // 800
#define SMEM_F4    (4 * WARP_F4)     // 3200
#define SMEM_BYTES (SMEM_F4 * 16)    // 51200 -> 4 CTAs/SM

__device__ __forceinline__ void cp16(uint32_t dst, const float4* src) {
    asm volatile("cp.async.ca.shared.global [%0], [%1], 16;" :: "r"(dst), "l"(src));
}
__device__ __forceinline__ void cp_commit() {
    asm volatile("cp.async.commit_group;");
}

__device__ __forceinline__ void map_step(float a1, float a2, float x,
                                         float& m00, float& m01, float& m10,
                                         float& m11, float& v0, float& v1)
{
    float t00 = -(a1*m00 + a2*m10);
    float t01 = -(a1*m01 + a2*m11);
    float tv0 = x - a1*v0 - a2*v1;
    m10 = m00; m11 = m01; v1 = v0;
    m00 = t00; m01 = t01; v0 = tv0;
}

__device__ __forceinline__ float4 shfl_up4(float4 v) {
    float4 r;
    r.x = __shfl_up_sync(FULLM, v.x, 1);
    r.y = __shfl_up_sync(FULLM, v.y, 1);
    r.z = __shfl_up_sync(FULLM, v.z, 1);
    r.w = __shfl_up_sync(FULLM, v.w, 1);
    return r;
}
__device__ __forceinline__ float4 shfl31_4(float4 v) {
    float4 r;
    r.x = __shfl_sync(FULLM, v.x, 31);
    r.y = __shfl_sync(FULLM, v.y, 31);
    r.z = __shfl_sync(FULLM, v.z, 31);
    r.w = __shfl_sync(FULLM, v.w, 31);
    return r;
}

struct Pre {                       // per-thread tile data in registers
    float4 ya, yb;                 // own y f4 groups G0+ga, G0+ga+1
    float4 a0, a1, a2, a3;         // Al f4s for the 8 samples
};

__global__ void __launch_bounds__(TPB, 4)
diffks_fused(const float* __restrict__ y, const float* __restrict__ Ae,
             const float* __restrict__ Al, float* __restrict__ out)
{
    extern __shared__ float4 sm[];

    const int tid  = threadIdx.x;
    const int lane = tid & 31;
    const int wrp  = tid >> 5;
    const int w    = blockIdx.x * 4 + wrp;        // global autonomous-warp id

    const int t0 = (int)(((long long)w * NTILES) / NWARPS);
    const int t1 = (int)(((long long)(w + 1) * NTILES) / NWARPS);

    float4* smW = sm + wrp * WARP_F4;
    const uint32_t smu = (uint32_t)__cvta_generic_to_shared(smW);

    // ---- stage warp-tile tau's Ae into private stage s ----
    auto stage_issue = [&](int tau, int s) {
        int br = tau / TROW, tr = tau - br * TROW;
        const float4* aeg = (const float4*)Ae + (size_t)br * AE_F4_ROW;
        const uint32_t sb = smu + (uint32_t)(s * STAGE_F4 * 16);
        int base = tr * 384;                       // G0*6
        #pragma unroll
        for (int j = 0; j < 12; j++) {             // 384 f4 -> quads pitch 25
            int f = lane + 32 * j;
            int gi = min(base + f, AE_F4_ROW - 1);
            int q = f / 24, k = f - 24 * q;
            cp16(sb + (uint32_t)((q * 25 + k) * 16), aeg + gi);
        }
        cp_commit();
    };

    // ---- per-thread register loads: y (2 f4) + Al (4 f4) ----
    auto load_pre = [&](int tau) {
        Pre r;
        int br = tau / TROW, tr = tau - br * TROW;
        const float4* ygr = (const float4*)y  + (size_t)br * Y_F4_ROW;
        const float4* alg = (const float4*)Al + (size_t)br * AL_F4_ROW;
        int G = tr * 64 + 2 * lane;
        r.ya = ygr[min(G,     YMAX)];
        r.yb = ygr[min(G + 1, YMAX)];
        int im = min(2 * G, AL_F4_ROW - 4);
        r.a0 = alg[im];     r.a1 = alg[im + 1];
        r.a2 = alg[im + 2]; r.a3 = alg[im + 3];
        return r;
    };

    // ---- prologue ----
    stage_issue(t0, 0);
    Pre prc = load_pre(t0);

    // previous-tile tail (y groups G0-2, G0-1) for lane 0's halo
    float4 pya, pyb;
    {
        int br0 = t0 / TROW, tr0 = t0 - br0 * TROW;
        const float4* ygr = (const float4*)y + (size_t)br0 * Y_F4_ROW;
        int G0 = tr0 * 64;
        pya = ygr[min(max(G0 - 2, 0), YMAX)];
        pyb = ygr[min(max(G0 - 1, 0), YMAX)];
    }

    // span entry state: exact zero at row start, else one-time 32-sample warmup
    float bs0 = 0.f, bs1 = 0.f;
    {
        int br0 = t0 / TROW, tr0 = t0 - br0 * TROW;
        if (tr0 != 0) {
            const float4* ygw  = (const float4*)y  + (size_t)br0 * Y_F4_ROW;
            const float4* aegw = (const float4*)Ae + (size_t)br0 * AE_F4_ROW;
            const float4* algw = (const float4*)Al + (size_t)br0 * AL_F4_ROW;
            int W  = tr0 * 64 - 8 + lane;          // lanes 0-7 carry real work
            int Wc = min(W, YMAX);
            float4 yv  = ygw[Wc];
            float4 yv1 = ygw[Wc - 1];
            float4 yv2 = ygw[Wc - 2];
            int ai = min(6 * W, AE_F4_ROW - 6);
            float4 e0 = aegw[ai],     e1 = aegw[ai + 1], e2 = aegw[ai + 2];
            float4 e3 = aegw[ai + 3], e4 = aegw[ai + 4], e5 = aegw[ai + 5];
            int li = min(2 * W, AL_F4_ROW - 2);
            float4 l0 = algw[li], l1 = algw[li + 1];

            float h0 = yv1.w, h1 = yv1.z, h2 = yv1.y, h3 = yv1.x;
            float h4 = yv2.w, h5 = yv2.z;
            float4 x4;
            x4.x = yv.x + e0.x*h0 + e0.y*h1 + e0.z*h2 + e0.w*h3 + e1.x*h4 + e1.y*h5;
            h5=h4; h4=h3; h3=h2; h2=h1; h1=h0; h0=yv.x;
            x4.y = yv.y + e1.z*h0 + e1.w*h1 + e2.x*h2 + e2.y*h3 + e2.z*h4 + e2.w*h5;
            h5=h4; h4=h3; h3=h2; h2=h1; h1=h0; h0=yv.y;
            x4.z = yv.z + e3.x*h0 + e3.y*h1 + e3.z*h2 + e3.w*h3 + e4.x*h4 + e4.y*h5;
            h5=h4; h4=h3; h3=h2; h2=h1; h1=h0; h0=yv.z;
            x4.w = yv.w + e4.z*h0 + e4.w*h1 + e5.x*h2 + e5.y*h3 + e5.z*h4 + e5.w*h5;

            float m00 = -l0.x, m01 = -l0.y, m10 = 1.f, m11 = 0.f, v0 = x4.x, v1 = 0.f;
            map_step(l0.z, l0.w, x4.y, m00, m01, m10, m11, v0, v1);
            map_step(l1.x, l1.y, x4.z, m00, m01, m10, m11, v0, v1);
            map_step(l1.z, l1.w, x4.w, m00, m01, m10, m11, v0, v1);
            #pragma unroll
            for (int d = 1; d <= 4; d <<= 1) {
                float om00 = __shfl_up_sync(FULLM, m00, d);
                float om01 = __shfl_up_sync(FULLM, m01, d);
                float om10 = __shfl_up_sync(FULLM, m10, d);
                float om11 = __shfl_up_sync(FULLM, m11, d);
                float ov0  = __shfl_up_sync(FULLM, v0,  d);
                float ov1  = __shfl_up_sync(FULLM, v1,  d);
                if (lane >= d) {
                    float n00 = m00*om00 + m01*om10;
                    float n01 = m00*om01 + m01*om11;
                    float n10 = m10*om00 + m11*om10;
                    float n11 = m10*om01 + m11*om11;
                    float nv0 = m00*ov0 + m01*ov1 + v0;
                    float nv1 = m10*ov0 + m11*ov1 + v1;
                    m00=n00; m01=n01; m10=n10; m11=n11; v0=nv0; v1=nv1;
                }
            }
            bs0 = __shfl_sync(FULLM, v0, 7);
            bs1 = __shfl_sync(FULLM, v1, 7);
        }
    }

    Pre prn = prc;

    for (int k = t0; k < t1; k++) {
        const int s = (k - t0) & 1;
        const bool more = (k + 1 < t1);
        if (more) { stage_issue(k + 1, s ^ 1); prn = load_pre(k + 1); }

        // pending: [stage k+1][stage k] -> retire stage k
        if (more) asm volatile("cp.async.wait_group 1;");
        else      asm volatile("cp.async.wait_group 0;");
        __syncwarp();

        const int br = k / TROW, tr = k - br * TROW;
        const int G0 = tr * 64;
        if (tr == 0) { bs0 = 0.f; bs1 = 0.f; }   // exact zero state at row start

        const float4* sAe = smW + s * STAGE_F4;
        const int ga = 2 * lane;

        // ---- y window: own groups + shuffled halo ----
        float4 ya = prc.ya, yb = prc.yb;
        float4 w0 = shfl_up4(ya);
        float4 w1 = shfl_up4(yb);
        if (lane == 0) {
            if (tr == 0) {
                w0 = make_float4(0.f, 0.f, 0.f, 0.f);
                w1 = make_float4(0.f, 0.f, 0.f, 0.f);
            } else {
                w0 = pya; w1 = pyb;
            }
        }
        // save this tile's tail for next tile's lane-0 halo
        pya = shfl31_4(ya);
        pyb = shfl31_4(yb);

        // ---- FIR ----
        float4 xa, xb;
        {
            const float4* aeP = &sAe[(ga >> 2) * 25 + (ga & 3) * 6];
            float4 e0 = aeP[0], e1 = aeP[1], e2 = aeP[2];
            float4 e3 = aeP[3], e4 = aeP[4], e5 = aeP[5];
            float h0 = w1.w, h1 = w1.z, h2 = w1.y, h3 = w1.x;
            float h4 = w0.w, h5 = w0.z;
            xa.x = ya.x + e0.x*h0 + e0.y*h1 + e0.z*h2 + e0.w*h3 + e1.x*h4 + e1.y*h5;
            h5=h4; h4=h3; h3=h2; h2=h1; h1=h0; h0=ya.x;
            xa.y = ya.y + e1.z*h0 + e1.w*h1 + e2.x*h2 + e2.y*h3 + e2.z*h4 + e2.w*h5;
            h5=h4; h4=h3; h3=h2; h2=h1; h1=h0; h0=ya.y;
            xa.z = ya.z + e3.x*h0 + e3.y*h1 + e3.z*h2 + e3.w*h3 + e4.x*h4 + e4.y*h5;
            h5=h4; h4=h3; h3=h2; h2=h1; h1=h0; h0=ya.z;
            xa.w = ya.w + e4.z*h0 + e4.w*h1 + e5.x*h2 + e5.y*h3 + e5.z*h4 + e5.w*h5;
        }
        {
            const int g = ga + 1;
            const float4* aeP = &sAe[(g >> 2) * 25 + (g & 3) * 6];
            float4 e0 = aeP[0], e1 = aeP[1], e2 = aeP[2];
            float4 e3 = aeP[3], e4 = aeP[4], e5 = aeP[5];
            float h0 = ya.w, h1 = ya.z, h2 = ya.y, h3 = ya.x;
            float h4 = w1.w, h5 = w1.z;
            xb.x = yb.x + e0.x*h0 + e0.y*h1 + e0.z*h2 + e0.w*h3 + e1.x*h4 + e1.y*h5;
            h5=h4; h4=h3; h3=h2; h2=h1; h1=h0; h0=yb.x;
            xb.y = yb.y + e1.z*h0 + e1.w*h1 + e2.x*h2 + e2.y*h3 + e2.z*h4 + e2.w*h5;
            h5=h4; h4=h3; h3=h2; h2=h1; h1=h0; h0=yb.y;
            xb.z = yb.z + e3.x*h0 + e3.y*h1 + e3.z*h2 + e3.w*h3 + e4.x*h4 + e4.y*h5;
            h5=h4; h4=h3; h3=h2; h2=h1; h1=h0; h0=yb.z;
            xb.w = yb.w + e4.z*h0 + e4.w*h1 + e5.x*h2 + e5.y*h3 + e5.z*h4 + e5.w*h5;
        }

        const float4 l0a = prc.a0, l1a = prc.a1, l0b = prc.a2, l1b = prc.a3;

        // ---- 8-step affine map ----
        float m00 = -l0a.x, m01 = -l0a.y, m10 = 1.f, m11 = 0.f, v0 = xa.x, v1 = 0.f;
        map_step(l0a.z, l0a.w, xa.y, m00, m01, m10, m11, v0, v1);
        map_step(l1a.x, l1a.y, xa.z, m00, m01, m10, m11, v0, v1);
        map_step(l1a.z, l1a.w, xa.w, m00, m01, m10, m11, v0, v1);
        map_step(l0b.x, l0b.y, xb.x, m00, m01, m10, m11, v0, v1);
        map_step(l0b.z, l0b.w, xb.y, m00, m01, m10, m11, v0, v1);
        map_step(l1b.x, l1b.y, xb.z, m00, m01, m10, m11, v0, v1);
        map_step(l1b.z, l1b.w, xb.w, m00, m01, m10, m11, v0, v1);

        // ---- 32-lane inclusive scan ----
        float im00 = m00, im01 = m01, im10 = m10, im11 = m11, iv0 = v0, iv1 = v1;
        #pragma unroll
        for (int d = 1; d <= 16; d <<= 1) {
            float om00 = __shfl_up_sync(FULLM, im00, d);
            float om01 = __shfl_up_sync(FULLM, im01, d);
            float om10 = __shfl_up_sync(FULLM, im10, d);
            float om11 = __shfl_up_sync(FULLM, im11, d);
            float ov0  = __shfl_up_sync(FULLM, iv0,  d);
            float ov1  = __shfl_up_sync(FULLM, iv1,  d);
            if (lane >= d) {
                float n00 = im00*om00 + im01*om10;
                float n01 = im00*om01 + im01*om11;
                float n10 = im10*om00 + im11*om10;
                float n11 = im10*om01 + im11*om11;
                float nv0 = im00*ov0 + im01*ov1 + iv0;
                float nv1 = im10*ov0 + im11*ov1 + iv1;
                im00=n00; im01=n01; im10=n10; im11=n11; iv0=nv0; iv1=nv1;
            }
        }
        // exclusive prefix
        float em00 = __shfl_up_sync(FULLM, im00, 1);
        float em01 = __shfl_up_sync(FULLM, im01, 1);
        float em10 = __shfl_up_sync(FULLM, im10, 1);
        float em11 = __shfl_up_sync(FULLM, im11, 1);
        float ev0  = __shfl_up_sync(FULLM, iv0,  1);
        float ev1  = __shfl_up_sync(FULLM, iv1,  1);
        if (lane == 0) { em00 = 1.f; em01 = 0.f; em10 = 0.f; em11 = 1.f; ev0 = 0.f; ev1 = 0.f; }

        // per-lane entry state from warp-carried bs
        float s1 = em00 * bs0 + em01 * bs1 + ev0;
        float s2 = em10 * bs0 + em11 * bs1 + ev1;

        // chain warp state through this tile's composite map (lane 31)
        {
            float c00 = __shfl_sync(FULLM, im00, 31);
            float c01 = __shfl_sync(FULLM, im01, 31);
            float c10 = __shfl_sync(FULLM, im10, 31);
            float c11 = __shfl_sync(FULLM, im11, 31);
            float cv0 = __shfl_sync(FULLM, iv0,  31);
            float cv1 = __shfl_sync(FULLM, iv1,  31);
            float n0 = c00 * bs0 + c01 * bs1 + cv0;
            float n1 = c10 * bs0 + c11 * bs1 + cv1;
            bs0 = n0; bs1 = n1;
        }

        // ---- replay 8 samples ----
        float4 o1, o2; float yo;
        yo = xa.x - l0a.x*s1 - l0a.y*s2;  s2 = s1; s1 = yo; o1.x = yo;
        yo = xa.y - l0a.z*s1 - l0a.w*s2;  s2 = s1; s1 = yo; o1.y = yo;
        yo = xa.z - l1a.x*s1 - l1a.y*s2;  s2 = s1; s1 = yo; o1.z = yo;
        yo = xa.w - l1a.z*s1 - l1a.w*s2;  s2 = s1; s1 = yo; o1.w = yo;
        yo = xb.x - l0b.x*s1 - l0b.y*s2;  s2 = s1; s1 = yo; o2.x = yo;
        yo = xb.y - l0b.z*s1 - l0b.w*s2;  s2 = s1; s1 = yo; o2.y = yo;
        yo = xb.z - l1b.x*s1 - l1b.y*s2;  s2 = s1; s1 = yo; o2.z = yo;
        yo = xb.w - l1b.z*s1 - l1b.w*s2;  s2 = s1; s1 = yo; o2.w = yo;

        float4* og = reinterpret_cast<float4*>(out + (size_t)br * TLEN);
        const int Gm = G0 + ga;
        if (Gm < T4)     og[Gm]     = o1;
        if (Gm + 1 < T4) og[Gm + 1] = o2;

        __syncwarp();
        prc = prn;
    }
}

extern "C" void kernel_launch(void* const* d_in, const int* in_sizes, int n_in,
                              void* d_out, int out_size)
{
    const float* y  = (const float*)d_in[0];
    const float* Ae = (const float*)d_in[1];
    const float* Al = (const float*)d_in[2];
    float* out = (float*)d_out;

    cudaFuncSetAttribute(diffks_fused,
                         cudaFuncAttributeMaxDynamicSharedMemorySize, SMEM_BYTES);

    diffks_fused<<<GRID, TPB, SMEM_BYTES>>>(y, Ae, Al, out);
}

// round 16
// speedup vs baseline: 1.4733x; 1.4733x over previous
#include <cuda_runtime.h>
#include <cstdint>

// DiffKS fused, warp-autonomous (R14 base = best): FIR (order 6) + order-2 IIR
// via warp affine scan (8 samples/thread), NO block barriers.
//   x[t]  = y[t] + sum_{k=1..6} Ae[t,k-1]*y[t-k]
//   out[t]= x[t] - a1[t]*out[t-1] - a2[t]*out[t-2]
// Each WARP owns ~9 consecutive 256-sample tiles: private double-buffered
// cp.async stage (y+Ae), register-prefetched Al, state chained in registers.
// R16 chain cuts vs R14: (1) post-scan w-trick: w_l = I_l(bs) then
// shfl_up(w,1) for entry state and shfl(w,31) for next-tile state -> 4 SHFLs
// instead of 12 (identical arithmetic); (2) 8-step map built as two parallel
// 4-step chains + compose (shorter serial latency).
// Row starts reset state exactly; mid-row span start runs one 32-sample warmup
// (|a|<=0.25 -> contraction ~0.64/step -> ~6e-7 << 1e-3 gate).

#define BATCH 48
#define TLEN  88200
#define T4    22050
#define Y_F4_ROW  22050
#define AE_F4_ROW 132300
#define AL_F4_ROW 44100
#define YMAX  (Y_F4_ROW - 1)

#define TPB    128
#define TROW   345                   // 64-f4 warp-tiles per row
#define NTILES (BATCH * TROW)        // 16560
#define GRID   444                   // 148 SMs * 3 CTAs
#define NWARPS (GRID * 4)            // 1776 autonomous warps (~9.3 tiles each)
#define FULLM  0xffffffffu

// per-warp stage layout (float4): y slots 0..67 (halo -2), pad to 72, Ae 16 quads * 25
#define STAGE_F4   472
#define WARP_F4    (2 * STAGE_F4)    // 944
#define SMEM_F4    (4 * WARP_F4)     // 3776
#define SMEM_BYTES (SMEM_F4 * 16)    // 60416 -> 3 CTAs/SM

__device__ __forceinline__ void cp16(uint32_t dst, const float4* src) {
    asm volatile("cp.async.ca.shared.global [%0], [%1], 16;" :: "r"(dst), "l"(src));
}
__device__ __forceinline__ void cp16z(uint32_t dst, const float4* src, int sz) {
    asm volatile("cp.async.ca.shared.global [%0], [%1], 16, %2;"
                 :: "r"(dst), "l"(src), "r"(sz));
}
__device__ __forceinline__ void cp_commit() {
    asm volatile("cp.async.commit_group;");
}

__device__ __forceinline__ void map_step(float a1, float a2, float x,
                                         float& m00, float& m01, float& m10,
                                         float& m11, float& v0, float& v1)
{
    float t00 = -(a1*m00 + a2*m10);
    float t01 = -(a1*m01 + a2*m11);
    float tv0 = x - a1*v0 - a2*v1;
    m10 = m00; m11 = m01; v1 = v0;
    m00 = t00; m01 = t01; v0 = tv0;
}

struct AlRegs { float4 a0, a1, a2, a3; };

__global__ void __launch_bounds__(TPB, 3)
diffks_fused(const float* __restrict__ y, const float* __restrict__ Ae,
             const float* __restrict__ Al, float* __restrict__ out)
{
    extern __shared__ float4 sm[];

    const int tid  = threadIdx.x;
    const int lane = tid & 31;
    const int wrp  = tid >> 5;
    const int w    = blockIdx.x * 4 + wrp;        // global autonomous-warp id

    const int t0 = (int)(((long long)w * NTILES) / NWARPS);
    const int t1 = (int)(((long long)(w + 1) * NTILES) / NWARPS);

    float4* smW = sm + wrp * WARP_F4;
    const uint32_t smu = (uint32_t)__cvta_generic_to_shared(smW);

    // ---- stage warp-tile tau (y + Ae) into private stage s; one commit ----
    auto stage_issue = [&](int tau, int s) {
        int br = tau / TROW, tr = tau - br * TROW;
        int G0 = tr * 64;
        const float4* yg  = (const float4*)y  + (size_t)br * Y_F4_ROW;
        const float4* aeg = (const float4*)Ae + (size_t)br * AE_F4_ROW;
        const uint32_t sb = smu + (uint32_t)(s * STAGE_F4 * 16);
        #pragma unroll
        for (int j = 0; j < 3; j++) {              // y: 68 f4 (2-f4 halo)
            int f = lane + 32 * j;
            if (f < 68) {
                int gi = G0 - 2 + f;
                int gc = min(max(gi, 0), YMAX);
                cp16z(sb + (uint32_t)(f * 16), yg + gc, (gi < 0) ? 0 : 16);
            }
        }
        #pragma unroll
        for (int j = 0; j < 12; j++) {             // Ae: 384 f4 -> quads pitch 25
            int f = lane + 32 * j;
            int gi = min(G0 * 6 + f, AE_F4_ROW - 1);
            int q = f / 24, k = f - 24 * q;
            cp16(sb + (uint32_t)((72 + q * 25 + k) * 16), aeg + gi);
        }
        cp_commit();
    };

    // ---- per-thread Al register loads (4 contiguous f4) ----
    auto load_al = [&](int tau) {
        AlRegs r;
        int br = tau / TROW, tr = tau - br * TROW;
        const float4* alg = (const float4*)Al + (size_t)br * AL_F4_ROW;
        int G = tr * 64 + 2 * lane;
        int im = min(2 * G, AL_F4_ROW - 4);
        r.a0 = alg[im];     r.a1 = alg[im + 1];
        r.a2 = alg[im + 2]; r.a3 = alg[im + 3];
        return r;
    };

    // ---- prologue ----
    stage_issue(t0, 0);
    AlRegs alc = load_al(t0);

    // span entry state: exact zero at row start, else one-time 32-sample warmup
    float bs0 = 0.f, bs1 = 0.f;
    {
        int br0 = t0 / TROW, tr0 = t0 - br0 * TROW;
        if (tr0 != 0) {
            const float4* ygw  = (const float4*)y  + (size_t)br0 * Y_F4_ROW;
            const float4* aegw = (const float4*)Ae + (size_t)br0 * AE_F4_ROW;
            const float4* algw = (const float4*)Al + (size_t)br0 * AL_F4_ROW;
            int W  = tr0 * 64 - 8 + lane;          // lanes 0-7 carry real work
            int Wc = min(W, YMAX);
            float4 yv  = ygw[Wc];
            float4 yv1 = ygw[Wc - 1];
            float4 yv2 = ygw[Wc - 2];
            int ai = min(6 * W, AE_F4_ROW - 6);
            float4 e0 = aegw[ai],     e1 = aegw[ai + 1], e2 = aegw[ai + 2];
            float4 e3 = aegw[ai + 3], e4 = aegw[ai + 4], e5 = aegw[ai + 5];
            int li = min(2 * W, AL_F4_ROW - 2);
            float4 l0 = algw[li], l1 = algw[li + 1];

            float h0 = yv1.w, h1 = yv1.z, h2 = yv1.y, h3 = yv1.x;
            float h4 = yv2.w, h5 = yv2.z;
            float4 x4;
            x4.x = yv.x + e0.x*h0 + e0.y*h1 + e0.z*h2 + e0.w*h3 + e1.x*h4 + e1.y*h5;
            h5=h4; h4=h3; h3=h2; h2=h1; h1=h0; h0=yv.x;
            x4.y = yv.y + e1.z*h0 + e1.w*h1 + e2.x*h2 + e2.y*h3 + e2.z*h4 + e2.w*h5;
            h5=h4; h4=h3; h3=h2; h2=h1; h1=h0; h0=yv.y;
            x4.z = yv.z + e3.x*h0 + e3.y*h1 + e3.z*h2 + e3.w*h3 + e4.x*h4 + e4.y*h5;
            h5=h4; h4=h3; h3=h2; h2=h1; h1=h0; h0=yv.z;
            x4.w = yv.w + e4.z*h0 + e4.w*h1 + e5.x*h2 + e5.y*h3 + e5.z*h4 + e5.w*h5;

            float m00 = -l0.x, m01 = -l0.y, m10 = 1.f, m11 = 0.f, v0 = x4.x, v1 = 0.f;
            map_step(l0.z, l0.w, x4.y, m00, m01, m10, m11, v0, v1);
            map_step(l1.x, l1.y, x4.z, m00, m01, m10, m11, v0, v1);
            map_step(l1.z, l1.w, x4.w, m00, m01, m10, m11, v0, v1);
            #pragma unroll
            for (int d = 1; d <= 4; d <<= 1) {
                float om00 = __shfl_up_sync(FULLM, m00, d);
                float om01 = __shfl_up_sync(FULLM, m01, d);
                float om10 = __shfl_up_sync(FULLM, m10, d);
                float om11 = __shfl_up_sync(FULLM, m11, d);
                float ov0  = __shfl_up_sync(FULLM, v0,  d);
                float ov1  = __shfl_up_sync(FULLM, v1,  d);
                if (lane >= d) {
                    float n00 = m00*om00 + m01*om10;
                    float n01 = m00*om01 + m01*om11;
                    float n10 = m10*om00 + m11*om10;
                    float n11 = m10*om01 + m11*om11;
                    float nv0 = m00*ov0 + m01*ov1 + v0;
                    float nv1 = m10*ov0 + m11*ov1 + v1;
                    m00=n00; m01=n01; m10=n10; m11=n11; v0=nv0; v1=nv1;
                }
            }
            bs0 = __shfl_sync(FULLM, v0, 7);
            bs1 = __shfl_sync(FULLM, v1, 7);
        }
    }

    AlRegs aln = alc;

    for (int k = t0; k < t1; k++) {
        const int s = (k - t0) & 1;
        const bool more = (k + 1 < t1);
        if (more) { stage_issue(k + 1, s ^ 1); aln = load_al(k + 1); }

        // pending: [stage k+1][stage k] -> retire stage k, then warp-sync
        if (more) asm volatile("cp.async.wait_group 1;");
        else      asm volatile("cp.async.wait_group 0;");
        __syncwarp();

        const int br = k / TROW, tr = k - br * TROW;
        const int G0 = tr * 64;
        if (tr == 0) { bs0 = 0.f; bs1 = 0.f; }   // exact zero state at row start

        const float4* sY  = smW + s * STAGE_F4;
        const float4* sAe = sY + 72;
        const int ga = 2 * lane;                  // local group a (b = ga+1)

        // y window: slots ga..ga+3  (slot f <-> f4 index G0-2+f)
        float4 w0 = sY[ga], w1 = sY[ga + 1], w2 = sY[ga + 2], w3 = sY[ga + 3];

        // ---- FIR from staged y/Ae ----
        float4 xa, xb;
        {
            const float4* aeP = &sAe[(ga >> 2) * 25 + (ga & 3) * 6];
            float4 e0 = aeP[0], e1 = aeP[1], e2 = aeP[2];
            float4 e3 = aeP[3], e4 = aeP[4], e5 = aeP[5];
            float h0 = w1.w, h1 = w1.z, h2 = w1.y, h3 = w1.x;
            float h4 = w0.w, h5 = w0.z;
            xa.x = w2.x + e0.x*h0 + e0.y*h1 + e0.z*h2 + e0.w*h3 + e1.x*h4 + e1.y*h5;
            h5=h4; h4=h3; h3=h2; h2=h1; h1=h0; h0=w2.x;
            xa.y = w2.y + e1.z*h0 + e1.w*h1 + e2.x*h2 + e2.y*h3 + e2.z*h4 + e2.w*h5;
            h5=h4; h4=h3; h3=h2; h2=h1; h1=h0; h0=w2.y;
            xa.z = w2.z + e3.x*h0 + e3.y*h1 + e3.z*h2 + e3.w*h3 + e4.x*h4 + e4.y*h5;
            h5=h4; h4=h3; h3=h2; h2=h1; h1=h0; h0=w2.z;
            xa.w = w2.w + e4.z*h0 + e4.w*h1 + e5.x*h2 + e5.y*h3 + e5.z*h4 + e5.w*h5;
        }
        {
            const int g = ga + 1;
            const float4* aeP = &sAe[(g >> 2) * 25 + (g & 3) * 6];
            float4 e0 = aeP[0], e1 = aeP[1], e2 = aeP[2];
            float4 e3 = aeP[3], e4 = aeP[4], e5 = aeP[5];
            float h0 = w2.w, h1 = w2.z, h2 = w2.y, h3 = w2.x;
            float h4 = w1.w, h5 = w1.z;
            xb.x = w3.x + e0.x*h0 + e0.y*h1 + e0.z*h2 + e0.w*h3 + e1.x*h4 + e1.y*h5;
            h5=h4; h4=h3; h3=h2; h2=h1; h1=h0; h0=w3.x;
            xb.y = w3.y + e1.z*h0 + e1.w*h1 + e2.x*h2 + e2.y*h3 + e2.z*h4 + e2.w*h5;
            h5=h4; h4=h3; h3=h2; h2=h1; h1=h0; h0=w3.y;
            xb.z = w3.z + e3.x*h0 + e3.y*h1 + e3.z*h2 + e3.w*h3 + e4.x*h4 + e4.y*h5;
            h5=h4; h4=h3; h3=h2; h2=h1; h1=h0; h0=w3.z;
            xb.w = w3.w + e4.z*h0 + e4.w*h1 + e5.x*h2 + e5.y*h3 + e5.z*h4 + e5.w*h5;
        }

        const float4 l0a = alc.a0, l1a = alc.a1, l0b = alc.a2, l1b = alc.a3;

        // ---- two parallel 4-step maps + compose (shorter serial chain) ----
        float a00 = -l0a.x, a01 = -l0a.y, a10 = 1.f, a11 = 0.f, av0 = xa.x, av1 = 0.f;
        map_step(l0a.z, l0a.w, xa.y, a00, a01, a10, a11, av0, av1);
        map_step(l1a.x, l1a.y, xa.z, a00, a01, a10, a11, av0, av1);
        map_step(l1a.z, l1a.w, xa.w, a00, a01, a10, a11, av0, av1);

        float b00 = -l0b.x, b01 = -l0b.y, b10 = 1.f, b11 = 0.f, bv0 = xb.x, bv1 = 0.f;
        map_step(l0b.z, l0b.w, xb.y, b00, b01, b10, b11, bv0, bv1);
        map_step(l1b.x, l1b.y, xb.z, b00, b01, b10, b11, bv0, bv1);
        map_step(l1b.z, l1b.w, xb.w, b00, b01, b10, b11, bv0, bv1);

        float im00 = b00*a00 + b01*a10;
        float im01 = b00*a01 + b01*a11;
        float im10 = b10*a00 + b11*a10;
        float im11 = b10*a01 + b11*a11;
        float iv0  = b00*av0 + b01*av1 + bv0;
        float iv1  = b10*av0 + b11*av1 + bv1;

        // ---- 32-lane inclusive scan ----
        #pragma unroll
        for (int d = 1; d <= 16; d <<= 1) {
            float om00 = __shfl_up_sync(FULLM, im00, d);
            float om01 = __shfl_up_sync(FULLM, im01, d);
            float om10 = __shfl_up_sync(FULLM, im10, d);
            float om11 = __shfl_up_sync(FULLM, im11, d);
            float ov0  = __shfl_up_sync(FULLM, iv0,  d);
            float ov1  = __shfl_up_sync(FULLM, iv1,  d);
            if (lane >= d) {
                float n00 = im00*om00 + im01*om10;
                float n01 = im00*om01 + im01*om11;
                float n10 = im10*om00 + im11*om10;
                float n11 = im10*om01 + im11*om11;
                float nv0 = im00*ov0 + im01*ov1 + iv0;
                float nv1 = im10*ov0 + im11*ov1 + iv1;
                im00=n00; im01=n01; im10=n10; im11=n11; iv0=nv0; iv1=nv1;
            }
        }

        // ---- w-trick: w_l = I_l(bs); entry = w_{lane-1}; next bs = w_31 ----
        float wv0 = im00 * bs0 + im01 * bs1 + iv0;
        float wv1 = im10 * bs0 + im11 * bs1 + iv1;
        float s1 = __shfl_up_sync(FULLM, wv0, 1);
        float s2 = __shfl_up_sync(FULLM, wv1, 1);
        if (lane == 0) { s1 = bs0; s2 = bs1; }
        bs0 = __shfl_sync(FULLM, wv0, 31);
        bs1 = __shfl_sync(FULLM, wv1, 31);

        // ---- replay 8 samples ----
        float4 o1, o2; float yo;
        yo = xa.x - l0a.x*s1 - l0a.y*s2;  s2 = s1; s1 = yo; o1.x = yo;
        yo = xa.y - l0a.z*s1 - l0a.w*s2;  s2 = s1; s1 = yo; o1.y = yo;
        yo = xa.z - l1a.x*s1 - l1a.y*s2;  s2 = s1; s1 = yo; o1.z = yo;
        yo = xa.w - l1a.z*s1 - l1a.w*s2;  s2 = s1; s1 = yo; o1.w = yo;
        yo = xb.x - l0b.x*s1 - l0b.y*s2;  s2 = s1; s1 = yo; o2.x = yo;
        yo = xb.y - l0b.z*s1 - l0b.w*s2;  s2 = s1; s1 = yo; o2.y = yo;
        yo = xb.z - l1b.x*s1 - l1b.y*s2;  s2 = s1; s1 = yo; o2.z = yo;
        yo = xb.w - l1b.z*s1 - l1b.w*s2;  s2 = s1; s1 = yo; o2.w = yo;

        float4* og = reinterpret_cast<float4*>(out + (size_t)br * TLEN);
        const int Gm = G0 + ga;
        if (Gm < T4)     og[Gm]     = o1;
        if (Gm + 1 < T4) og[Gm + 1] = o2;

        __syncwarp();            // all lanes done reading stage s before refill
        alc = aln;
    }
}

extern "C" void kernel_launch(void* const* d_in, const int* in_sizes, int n_in,
                              void* d_out, int out_size)
{
    const float* y  = (const float*)d_in[0];
    const float* Ae = (const float*)d_in[1];
    const float* Al = (const float*)d_in[2];
    float* out = (float*)d_out;

    cudaFuncSetAttribute(diffks_fused,
                         cudaFuncAttributeMaxDynamicSharedMemorySize, SMEM_BYTES);

    diffks_fused<<<GRID, TPB, SMEM_BYTES>>>(y, Ae, Al, out);
}